// round 3
// baseline (speedup 1.0000x reference)
#include <cuda_runtime.h>
#include <cuda_bf16.h>
#include <cstdint>

// ModalConditionedRPE, GB300 sm_103a — fused single kernel.
//
// out[i,j] = b2 + sum_h relu(P[i,h] + Q[j,h]) * W2[h]
//   P[i,h] = x_i*W1[0,h] + y_i*W1[1,h] + s_mean[i]*W1[34,h] + Cmod[h]
//   Q[j,h] = -x_j*W1[0,h] - y_j*W1[1,h] + s_mean[j]*W1[35,h]
//   Cmod[h] = sum_k me[q,k]*W1[2+k,h] + me[km,k]*W1[18+k,h] + b1[h]
// s_mean: jax.image.resize 80->40 linear WITH antialias (4-tap triangle,
// edge-renormalized), mean over batch of 4. (Validated: rel_err 7.4e-8.)
//
// Each block computes its own 64-row P tile and 64-row Q tile in smem
// (prologue), then runs the 64x64 output tile with 4x4 register blocking,
// packed f32x2 math. __launch_bounds__(256,5) targets <=51 regs so all 625
// blocks are co-resident (5/SM max) -> better latency hiding, no tail wave.

#define NPIX 1600
#define HDIM 64
#define PAD  66   // smem row stride in floats

typedef unsigned long long u64;
union F2u { u64 u; float2 f; };

__device__ __forceinline__ u64 add2(u64 a, u64 b) {
    u64 r; asm("add.rn.f32x2 %0, %1, %2;" : "=l"(r) : "l"(a), "l"(b)); return r;
}
__device__ __forceinline__ u64 fma2(u64 a, u64 b, u64 c) {
    u64 r; asm("fma.rn.f32x2 %0, %1, %2, %3;" : "=l"(r) : "l"(a), "l"(b), "l"(c)); return r;
}

// 4-tap antialiased triangle weights for 80->40 downsample.
__device__ __forceinline__ void resize_taps(int o, float* w, int& t0) {
    t0 = 2 * o - 1;
    float ww[4] = { 0.25f, 0.75f, 0.75f, 0.25f };
    float s = 0.f;
#pragma unroll
    for (int k = 0; k < 4; k++) {
        int ii = t0 + k;
        if (ii < 0 || ii >= 80) ww[k] = 0.f;
        s += ww[k];
    }
    float inv = 1.f / s;
#pragma unroll
    for (int k = 0; k < 4; k++) w[k] = ww[k] * inv;
}

__device__ __forceinline__ float smean_pixel(const float* __restrict__ smap, int i) {
    int iy = i / 40, ix = i % 40;
    float wy[4], wx[4]; int ty0, tx0;
    resize_taps(iy, wy, ty0);
    resize_taps(ix, wx, tx0);
    float s = 0.f;
#pragma unroll
    for (int b = 0; b < 4; b++) {
        const float* base = smap + b * 6400;
#pragma unroll
        for (int a = 0; a < 4; a++) {
            if (wy[a] == 0.f) continue;
            int yy = ty0 + a;
            float rowacc = 0.f;
#pragma unroll
            for (int c = 0; c < 4; c++) {
                if (wx[c] == 0.f) continue;
                rowacc += wx[c] * base[yy * 80 + tx0 + c];
            }
            s += wy[a] * rowacc;
        }
    }
    return s * 0.25f;
}

__global__ __launch_bounds__(256, 5) void rpe_fused_kernel(
    const float* __restrict__ smap,   // (4,1,80,80)
    const float* __restrict__ me,     // (3,16)
    const float* __restrict__ W1,     // (36,64)
    const float* __restrict__ b1,     // (64)
    const int*   __restrict__ qmod,
    const int*   __restrict__ kmod,
    const float* __restrict__ W2,     // (64)
    const float* __restrict__ b2,     // (1)
    float*       __restrict__ out)    // (1600,1600)
{
    __shared__ __align__(16) float Ps[64 * PAD];
    __shared__ __align__(16) float Qs[64 * PAD];
    __shared__ __align__(16) float w2s[HDIM];
    __shared__ float smi[64], smj[64], cm[HDIM];

    const int t  = threadIdx.x;
    const int bi = blockIdx.y * 64;
    const int bj = blockIdx.x * 64;

    // ---- Phase 1: s_mean for this block's 64 i-pixels and 64 j-pixels,
    //      Cmod[h], and w2 staging. ----
    if (t < 64) {
        smi[t] = smean_pixel(smap, bi + t);
    } else if (t < 128) {
        smj[t - 64] = smean_pixel(smap, bj + (t - 64));
    } else if (t < 192) {
        int h = t - 128;
        int q = qmod[0], km = kmod[0];
        float c = b1[h];
#pragma unroll
        for (int kk = 0; kk < 16; kk++) {
            c += me[q  * 16 + kk] * W1[(2  + kk) * HDIM + h];
            c += me[km * 16 + kk] * W1[(18 + kk) * HDIM + h];
        }
        cm[h] = c;
    } else {
        w2s[t - 192] = W2[t - 192];
    }
    __syncthreads();

    // ---- Phase 2: build P/Q tiles in smem. 64 rows x 64 h each,
    //      8192 entries / 256 threads = 32 per thread (coalesced h). ----
    for (int p = t; p < 64 * HDIM; p += 256) {
        int r = p >> 6, h = p & 63;
        float w0  = W1[h];
        float w1  = W1[HDIM + h];
        float wsi = W1[34 * HDIM + h];
        float wsj = W1[35 * HDIM + h];
        {
            int i = bi + r;
            float x = -0.5f + (float)(i % 40) * (1.0f / 39.0f);
            float y = -0.5f + (float)(i / 40) * (1.0f / 39.0f);
            Ps[r * PAD + h] = x * w0 + y * w1 + smi[r] * wsi + cm[h];
        }
        {
            int j = bj + r;
            float x = -0.5f + (float)(j % 40) * (1.0f / 39.0f);
            float y = -0.5f + (float)(j / 40) * (1.0f / 39.0f);
            Qs[r * PAD + h] = -x * w0 - y * w1 + smj[r] * wsj;
        }
    }
    __syncthreads();

    // ---- Phase 3: main 64x64 tile, 4x4 per thread, packed f32x2. ----
    const int tx = t & 15;   // j group (stride 16)
    const int ty = t >> 4;   // i group (stride 16)

    const float* psB = &Ps[ty * PAD];
    const float* qsB = &Qs[tx * PAD];

    u64 acc[4][4];
#pragma unroll
    for (int r = 0; r < 4; r++)
#pragma unroll
        for (int c = 0; c < 4; c++) acc[r][c] = 0ull;

#pragma unroll 4
    for (int hp = 0; hp < 32; hp++) {
        u64 w2p = *(const u64*)&w2s[2 * hp];
        u64 b[4];
#pragma unroll
        for (int c = 0; c < 4; c++)
            b[c] = *(const u64*)&qsB[(16 * c) * PAD + 2 * hp];
#pragma unroll
        for (int r = 0; r < 4; r++) {
            u64 a = *(const u64*)&psB[(16 * r) * PAD + 2 * hp];
#pragma unroll
            for (int c = 0; c < 4; c++) {
                F2u u;
                u.u = add2(a, b[c]);             // FADD2 (fma pipe)
                u.f.x = fmaxf(u.f.x, 0.0f);      // FMNMX (alu pipe)
                u.f.y = fmaxf(u.f.y, 0.0f);
                acc[r][c] = fma2(u.u, w2p, acc[r][c]);  // FFMA2 (fma pipe)
            }
        }
    }

    const float bb = b2[0];
#pragma unroll
    for (int r = 0; r < 4; r++) {
        int gi = bi + ty + 16 * r;
#pragma unroll
        for (int c = 0; c < 4; c++) {
            int gj = bj + tx + 16 * c;
            F2u v; v.u = acc[r][c];
            out[gi * NPIX + gj] = v.f.x + v.f.y + bb;
        }
    }
}

// metadata order: h, w, q_mod, k_mod, structure_map, mod_embed, W1, b1, W2, b2
extern "C" void kernel_launch(void* const* d_in, const int* in_sizes, int n_in,
                              void* d_out, int out_size)
{
    const int*   qmod = (const int*)d_in[2];
    const int*   kmod = (const int*)d_in[3];
    const float* smap = (const float*)d_in[4];
    const float* me   = (const float*)d_in[5];
    const float* W1   = (const float*)d_in[6];
    const float* b1   = (const float*)d_in[7];
    const float* W2   = (const float*)d_in[8];
    const float* b2   = (const float*)d_in[9];
    float* out = (float*)d_out;

    rpe_fused_kernel<<<dim3(25, 25), 256>>>(smap, me, W1, b1, qmod, kmod, W2, b2, out);
}

// round 4
// speedup vs baseline: 1.1923x; 1.1923x over previous
#include <cuda_runtime.h>
#include <cuda_bf16.h>
#include <cstdint>

// ModalConditionedRPE, GB300 sm_103a. Two kernels (fusion regressed in R3).
//
// out[i,j] = b2 + sum_h relu(P[i,h] + Q[j,h]) * W2[h]
//   P[i,h] = x_i*W1[0,h] + y_i*W1[1,h] + s_mean[i]*W1[34,h] + Cmod[h]
//   Q[j,h] = -x_j*W1[0,h] - y_j*W1[1,h] + s_mean[j]*W1[35,h]
// s_mean: jax.image.resize 80->40 linear antialias (4-tap triangle,
// edge-renormalized), mean over batch of 4. (Validated rel_err 7.4e-8.)

#define NPIX 1600
#define HDIM 64
#define PAD  66   // smem row stride in floats (conflict-free for tx stride)

typedef unsigned long long u64;
union F2u { u64 u; float2 f; };

__device__ __forceinline__ u64 add2(u64 a, u64 b) {
    u64 r; asm("add.rn.f32x2 %0, %1, %2;" : "=l"(r) : "l"(a), "l"(b)); return r;
}
__device__ __forceinline__ u64 fma2(u64 a, u64 b, u64 c) {
    u64 r; asm("fma.rn.f32x2 %0, %1, %2, %3;" : "=l"(r) : "l"(a), "l"(b), "l"(c)); return r;
}

__device__ float g_P[NPIX * HDIM];
__device__ float g_Q[NPIX * HDIM];

// 4-tap antialiased triangle weights for the 80->40 downsample.
__device__ __forceinline__ void resize_taps(int o, float* w, int& t0) {
    t0 = 2 * o - 1;
    float ww[4] = { 0.25f, 0.75f, 0.75f, 0.25f };
    float s = 0.f;
#pragma unroll
    for (int k = 0; k < 4; k++) {
        int ii = t0 + k;
        if (ii < 0 || ii >= 80) ww[k] = 0.f;
        s += ww[k];
    }
    float inv = 1.f / s;
#pragma unroll
    for (int k = 0; k < 4; k++) w[k] = ww[k] * inv;
}

// Kernel 1: grid 25 x 256. Block covers pixels [64*bid, 64*bid+64).
// Phase A: s_mean, one thread per (pixel,batch): 16 taps each, shfl-reduce.
// Phase B: Cmod[h] (64 threads).
// Phase C: P/Q rows for the 64 pixels (coalesced over h).
__global__ __launch_bounds__(256) void precompute_kernel(
    const float* __restrict__ smap,   // (4,1,80,80)
    const float* __restrict__ me,     // (3,16)
    const float* __restrict__ W1,     // (36,64)
    const float* __restrict__ b1,     // (64)
    const int*   __restrict__ qmod,
    const int*   __restrict__ kmod)
{
    __shared__ float sm[64];
    __shared__ float cm[HDIM];
    const int t  = threadIdx.x;
    const int i0 = blockIdx.x * 64;

    // Phase A: t -> (pixel t>>2, batch t&3)
    {
        int li = t >> 2, b = t & 3;
        int i  = i0 + li;
        int iy = i / 40, ix = i % 40;
        float wy[4], wx[4]; int ty0, tx0;
        resize_taps(iy, wy, ty0);
        resize_taps(ix, wx, tx0);
        const float* base = smap + b * 6400;
        float s = 0.f;
#pragma unroll
        for (int a = 0; a < 4; a++) {
            if (wy[a] == 0.f) continue;
            int yy = ty0 + a;
            float rowacc = 0.f;
#pragma unroll
            for (int c = 0; c < 4; c++) {
                if (wx[c] == 0.f) continue;
                rowacc += wx[c] * base[yy * 80 + tx0 + c];
            }
            s += wy[a] * rowacc;
        }
        s += __shfl_xor_sync(0xffffffffu, s, 1);
        s += __shfl_xor_sync(0xffffffffu, s, 2);
        if (b == 0) sm[li] = s * 0.25f;
    }
    // Phase B: Cmod
    if (t >= 128 && t < 192) {
        int h = t - 128;
        int q = qmod[0], km = kmod[0];
        float c = b1[h];
#pragma unroll
        for (int kk = 0; kk < 16; kk++) {
            c += me[q  * 16 + kk] * W1[(2  + kk) * HDIM + h];
            c += me[km * 16 + kk] * W1[(18 + kk) * HDIM + h];
        }
        cm[h] = c;
    }
    __syncthreads();

    // Phase C: 64 pixels x 64 h = 4096 entries; 16 per thread.
    for (int p = t; p < 64 * HDIM; p += 256) {
        int r = p >> 6, h = p & 63;
        int i  = i0 + r;
        float x = -0.5f + (float)(i % 40) * (1.0f / 39.0f);
        float y = -0.5f + (float)(i / 40) * (1.0f / 39.0f);
        float w0  = W1[h];
        float w1  = W1[HDIM + h];
        float sv  = sm[r];
        g_P[i * HDIM + h] =  x * w0 + y * w1 + sv * W1[34 * HDIM + h] + cm[h];
        g_Q[i * HDIM + h] = -x * w0 - y * w1 + sv * W1[35 * HDIM + h];
    }
}

// Kernel 2: 64x64 tile / block, 4x4 per thread, packed f32x2.
// Register-lean loop (preload b[4]+w2, stream a) targeting 48 regs so 5
// blocks/SM -> all 625 blocks co-resident in one wave.
__global__ __launch_bounds__(256, 5) void rpe_main_kernel(
    const float* __restrict__ W2,   // (64)
    const float* __restrict__ b2,   // (1)
    float*       __restrict__ out)  // (1600,1600)
{
    __shared__ __align__(16) float Ps[64 * PAD];
    __shared__ __align__(16) float Qs[64 * PAD];
    __shared__ __align__(16) float w2s[HDIM];

    const int t  = threadIdx.x;
    const int bi = blockIdx.y * 64;
    const int bj = blockIdx.x * 64;

    // Tile fill: 64 rows x 32 float2 per tile; 8 float2 each thread.
#pragma unroll
    for (int k = t; k < 64 * 32; k += 256) {
        int r = k >> 5, c = k & 31;
        float2 vp = *(const float2*)&g_P[(bi + r) * HDIM + 2 * c];
        float2 vq = *(const float2*)&g_Q[(bj + r) * HDIM + 2 * c];
        *(float2*)&Ps[r * PAD + 2 * c] = vp;
        *(float2*)&Qs[r * PAD + 2 * c] = vq;
    }
    if (t < HDIM) w2s[t] = W2[t];
    __syncthreads();

    const int tx = t & 15;   // j group (stride 16)
    const int ty = t >> 4;   // i group (stride 16)

    const float* psB = &Ps[ty * PAD];
    const float* qsB = &Qs[tx * PAD];

    u64 acc[4][4];
#pragma unroll
    for (int r = 0; r < 4; r++)
#pragma unroll
        for (int c = 0; c < 4; c++) acc[r][c] = 0ull;

#pragma unroll 4
    for (int hp = 0; hp < 32; hp++) {
        u64 w2p = *(const u64*)&w2s[2 * hp];
        u64 b[4];
#pragma unroll
        for (int c = 0; c < 4; c++)
            b[c] = *(const u64*)&qsB[(16 * c) * PAD + 2 * hp];
#pragma unroll
        for (int r = 0; r < 4; r++) {
            u64 a = *(const u64*)&psB[(16 * r) * PAD + 2 * hp];
#pragma unroll
            for (int c = 0; c < 4; c++) {
                F2u u;
                u.u = add2(a, b[c]);             // FADD2 (fma pipe)
                u.f.x = fmaxf(u.f.x, 0.0f);      // FMNMX (alu pipe)
                u.f.y = fmaxf(u.f.y, 0.0f);
                acc[r][c] = fma2(u.u, w2p, acc[r][c]);  // FFMA2 (fma pipe)
            }
        }
    }

    const float bb = b2[0];
#pragma unroll
    for (int r = 0; r < 4; r++) {
        int gi = bi + ty + 16 * r;
#pragma unroll
        for (int c = 0; c < 4; c++) {
            int gj = bj + tx + 16 * c;
            F2u v; v.u = acc[r][c];
            out[gi * NPIX + gj] = v.f.x + v.f.y + bb;
        }
    }
}

// metadata order: h, w, q_mod, k_mod, structure_map, mod_embed, W1, b1, W2, b2
extern "C" void kernel_launch(void* const* d_in, const int* in_sizes, int n_in,
                              void* d_out, int out_size)
{
    const int*   qmod = (const int*)d_in[2];
    const int*   kmod = (const int*)d_in[3];
    const float* smap = (const float*)d_in[4];
    const float* me   = (const float*)d_in[5];
    const float* W1   = (const float*)d_in[6];
    const float* b1   = (const float*)d_in[7];
    const float* W2   = (const float*)d_in[8];
    const float* b2   = (const float*)d_in[9];
    float* out = (float*)d_out;

    precompute_kernel<<<25, 256>>>(smap, me, W1, b1, qmod, kmod);
    rpe_main_kernel<<<dim3(25, 25), 256>>>(W2, b2, out);
}

// round 5
// speedup vs baseline: 1.3671x; 1.1466x over previous
#include <cuda_runtime.h>
#include <cuda_bf16.h>
#include <cstdint>

// ModalConditionedRPE, GB300 sm_103a. Two kernels.
// R5 = R2 main kernel (proven 22.6us: batched a[4]+b[4] LDS front-load,
// unroll 8, 56 regs / 4 blocks/SM) + R4 precompute (proven ~2.8us).
// R3 fusion and R4 "lean-register" restructure both regressed; reverted.
//
// out[i,j] = b2 + sum_h relu(P[i,h] + Q[j,h]) * W2[h]
//   P[i,h] = x_i*W1[0,h] + y_i*W1[1,h] + s_mean[i]*W1[34,h] + Cmod[h]
//   Q[j,h] = -x_j*W1[0,h] - y_j*W1[1,h] + s_mean[j]*W1[35,h]
// s_mean: jax.image.resize 80->40 linear antialias (4-tap triangle,
// edge-renormalized), mean over batch of 4. (Validated rel_err 7.4e-8.)

#define NPIX 1600
#define HDIM 64
#define PAD  66   // smem row stride in floats (conflict-free for tx stride)

typedef unsigned long long u64;
union F2u { u64 u; float2 f; };

__device__ __forceinline__ u64 add2(u64 a, u64 b) {
    u64 r; asm("add.rn.f32x2 %0, %1, %2;" : "=l"(r) : "l"(a), "l"(b)); return r;
}
__device__ __forceinline__ u64 fma2(u64 a, u64 b, u64 c) {
    u64 r; asm("fma.rn.f32x2 %0, %1, %2, %3;" : "=l"(r) : "l"(a), "l"(b), "l"(c)); return r;
}
__device__ __forceinline__ void stg_cs(float* p, float v) {
    asm volatile("st.global.cs.f32 [%0], %1;" :: "l"(p), "f"(v) : "memory");
}

__device__ float g_P[NPIX * HDIM];
__device__ float g_Q[NPIX * HDIM];

// 4-tap antialiased triangle weights for the 80->40 downsample.
__device__ __forceinline__ void resize_taps(int o, float* w, int& t0) {
    t0 = 2 * o - 1;
    float ww[4] = { 0.25f, 0.75f, 0.75f, 0.25f };
    float s = 0.f;
#pragma unroll
    for (int k = 0; k < 4; k++) {
        int ii = t0 + k;
        if (ii < 0 || ii >= 80) ww[k] = 0.f;
        s += ww[k];
    }
    float inv = 1.f / s;
#pragma unroll
    for (int k = 0; k < 4; k++) w[k] = ww[k] * inv;
}

// Kernel 1 (R4 version): grid 25 x 256. Block covers pixels [64*bid, +64).
// Phase A: s_mean, one thread per (pixel,batch), shfl-reduce over batch.
// Phase B: Cmod[h]. Phase C: P/Q rows (coalesced over h).
__global__ __launch_bounds__(256) void precompute_kernel(
    const float* __restrict__ smap,   // (4,1,80,80)
    const float* __restrict__ me,     // (3,16)
    const float* __restrict__ W1,     // (36,64)
    const float* __restrict__ b1,     // (64)
    const int*   __restrict__ qmod,
    const int*   __restrict__ kmod)
{
    __shared__ float sm[64];
    __shared__ float cm[HDIM];
    const int t  = threadIdx.x;
    const int i0 = blockIdx.x * 64;

    // Phase A: t -> (pixel t>>2, batch t&3)
    {
        int li = t >> 2, b = t & 3;
        int i  = i0 + li;
        int iy = i / 40, ix = i % 40;
        float wy[4], wx[4]; int ty0, tx0;
        resize_taps(iy, wy, ty0);
        resize_taps(ix, wx, tx0);
        const float* base = smap + b * 6400;
        float s = 0.f;
#pragma unroll
        for (int a = 0; a < 4; a++) {
            if (wy[a] == 0.f) continue;
            int yy = ty0 + a;
            float rowacc = 0.f;
#pragma unroll
            for (int c = 0; c < 4; c++) {
                if (wx[c] == 0.f) continue;
                rowacc += wx[c] * base[yy * 80 + tx0 + c];
            }
            s += wy[a] * rowacc;
        }
        s += __shfl_xor_sync(0xffffffffu, s, 1);
        s += __shfl_xor_sync(0xffffffffu, s, 2);
        if (b == 0) sm[li] = s * 0.25f;
    }
    // Phase B: Cmod
    if (t >= 128 && t < 192) {
        int h = t - 128;
        int q = qmod[0], km = kmod[0];
        float c = b1[h];
#pragma unroll
        for (int kk = 0; kk < 16; kk++) {
            c += me[q  * 16 + kk] * W1[(2  + kk) * HDIM + h];
            c += me[km * 16 + kk] * W1[(18 + kk) * HDIM + h];
        }
        cm[h] = c;
    }
    __syncthreads();

    // Phase C: 64 pixels x 64 h = 4096 entries; 16 per thread.
    for (int p = t; p < 64 * HDIM; p += 256) {
        int r = p >> 6, h = p & 63;
        int i  = i0 + r;
        float x = -0.5f + (float)(i % 40) * (1.0f / 39.0f);
        float y = -0.5f + (float)(i / 40) * (1.0f / 39.0f);
        float w0  = W1[h];
        float w1  = W1[HDIM + h];
        float sv  = sm[r];
        g_P[i * HDIM + h] =  x * w0 + y * w1 + sv * W1[34 * HDIM + h] + cm[h];
        g_Q[i * HDIM + h] = -x * w0 - y * w1 + sv * W1[35 * HDIM + h];
    }
}

// Kernel 2 (R2 version): 64x64 tile / block, 4x4 per thread, packed f32x2,
// batched a[4]+b[4]+w2 LDS front-load per hp (MLP~9), unroll 8.
__global__ __launch_bounds__(256) void rpe_main_kernel(
    const float* __restrict__ W2,   // (64)
    const float* __restrict__ b2,   // (1)
    float*       __restrict__ out)  // (1600,1600)
{
    __shared__ __align__(16) float Ps[64 * PAD];
    __shared__ __align__(16) float Qs[64 * PAD];
    __shared__ __align__(16) float w2s[HDIM];

    const int t  = threadIdx.x;
    const int bi = blockIdx.y * 64;
    const int bj = blockIdx.x * 64;

    // Tile fill: 64 rows x 32 float2 per tile; 8 float2 each thread.
#pragma unroll
    for (int k = t; k < 64 * 32; k += 256) {
        int r = k >> 5, c = k & 31;
        float2 vp = *(const float2*)&g_P[(bi + r) * HDIM + 2 * c];
        float2 vq = *(const float2*)&g_Q[(bj + r) * HDIM + 2 * c];
        *(float2*)&Ps[r * PAD + 2 * c] = vp;
        *(float2*)&Qs[r * PAD + 2 * c] = vq;
    }
    if (t < HDIM) w2s[t] = W2[t];
    __syncthreads();

    const int tx = t & 15;   // j group (stride 16)
    const int ty = t >> 4;   // i group (stride 16)

    u64 acc[4][4];
#pragma unroll
    for (int r = 0; r < 4; r++)
#pragma unroll
        for (int c = 0; c < 4; c++) acc[r][c] = 0ull;

#pragma unroll 8
    for (int hp = 0; hp < 32; hp++) {
        u64 w2p = *(const u64*)&w2s[2 * hp];
        u64 a[4], b[4];
#pragma unroll
        for (int r = 0; r < 4; r++)
            a[r] = *(const u64*)&Ps[(ty + 16 * r) * PAD + 2 * hp];
#pragma unroll
        for (int c = 0; c < 4; c++)
            b[c] = *(const u64*)&Qs[(tx + 16 * c) * PAD + 2 * hp];

#pragma unroll
        for (int r = 0; r < 4; r++) {
#pragma unroll
            for (int c = 0; c < 4; c++) {
                F2u u;
                u.u = add2(a[r], b[c]);          // FADD2 (fma pipe)
                u.f.x = fmaxf(u.f.x, 0.0f);      // FMNMX (alu pipe)
                u.f.y = fmaxf(u.f.y, 0.0f);
                acc[r][c] = fma2(u.u, w2p, acc[r][c]);  // FFMA2 (fma pipe)
            }
        }
    }

    const float bb = b2[0];
#pragma unroll
    for (int r = 0; r < 4; r++) {
        int gi = bi + ty + 16 * r;
#pragma unroll
        for (int c = 0; c < 4; c++) {
            int gj = bj + tx + 16 * c;
            F2u v; v.u = acc[r][c];
            stg_cs(&out[gi * NPIX + gj], v.f.x + v.f.y + bb);
        }
    }
}

// metadata order: h, w, q_mod, k_mod, structure_map, mod_embed, W1, b1, W2, b2
extern "C" void kernel_launch(void* const* d_in, const int* in_sizes, int n_in,
                              void* d_out, int out_size)
{
    const int*   qmod = (const int*)d_in[2];
    const int*   kmod = (const int*)d_in[3];
    const float* smap = (const float*)d_in[4];
    const float* me   = (const float*)d_in[5];
    const float* W1   = (const float*)d_in[6];
    const float* b1   = (const float*)d_in[7];
    const float* W2   = (const float*)d_in[8];
    const float* b2   = (const float*)d_in[9];
    float* out = (float*)d_out;

    precompute_kernel<<<25, 256>>>(smap, me, W1, b1, qmod, kmod);
    rpe_main_kernel<<<dim3(25, 25), 256>>>(W2, b2, out);
}